// round 14
// baseline (speedup 1.0000x reference)
#include <cuda_runtime.h>
#include <cstdint>

#define NPTS 30000
#define NHALF 15000
#define CDIM 128
#define HEADS 8
#define DHEAD 16
#define SNBR 16
#define OSDIM 16
#define EPSV 1e-5f

typedef unsigned long long u64;

// packed f32x2 helpers (FFMA2 path — PTX-only on sm_103a)
#define F32X2_FMA(d, a, b, c) \
    asm("fma.rn.f32x2 %0, %1, %2, %3;" : "=l"(d) : "l"(a), "l"(b), "l"(c))
#define F32X2_ADD(d, a, b) \
    asm("add.rn.f32x2 %0, %1, %2;" : "=l"(d) : "l"(a), "l"(b))
#define F32X2_MUL(d, a, b) \
    asm("mul.rn.f32x2 %0, %1, %2;" : "=l"(d) : "l"(a), "l"(b))

__device__ __forceinline__ u64 pack2(float lo, float hi) {
    u64 r; asm("mov.b64 %0, {%1, %2};" : "=l"(r) : "f"(lo), "f"(hi)); return r;
}
__device__ __forceinline__ u64 dup2(float x) {
    u64 r; asm("mov.b64 %0, {%1, %1};" : "=l"(r) : "f"(x)); return r;
}
__device__ __forceinline__ float2 unpack2(u64 v) {
    float lo, hi; asm("mov.b64 {%0, %1}, %2;" : "=f"(lo), "=f"(hi) : "l"(v));
    return make_float2(lo, hi);
}
__device__ __forceinline__ u64 relu2(u64 x) {
    float2 f = unpack2(x);
    return pack2(fmaxf(f.x, 0.f), fmaxf(f.y, 0.f));
}

#define NEG1P 0xBF800000BF800000ULL   // (-1.0f, -1.0f)

// tf32 helpers
__device__ __forceinline__ uint32_t f2tf(float f) {
    uint32_t r; asm("cvt.rna.tf32.f32 %0, %1;" : "=r"(r) : "f"(f)); return r;
}
#define MMA_TF32(c, a, b) \
    asm("mma.sync.aligned.m16n8k8.row.col.f32.tf32.tf32.f32 " \
        "{%0,%1,%2,%3}, {%4,%5,%6,%7}, {%8,%9}, {%0,%1,%2,%3};" \
        : "+f"((c)[0]), "+f"((c)[1]), "+f"((c)[2]), "+f"((c)[3]) \
        : "r"((a)[0]), "r"((a)[1]), "r"((a)[2]), "r"((a)[3]), \
          "r"((b)[0]), "r"((b)[1]))

// ---------------------------------------------------------------------------
// Block-invariant parameters. Only UNIFORM-indexed arrays live here (loop-
// index addressing -> LDCU, floor 1). Divergently-indexed Wp2/bp2 go to smem.
// ---------------------------------------------------------------------------
struct __align__(16) CParams {
    float Ww1[DHEAD * OSDIM];   // 256
    float gw1[DHEAD];
    float betaw1[DHEAD];
    float bw1[OSDIM];
    float gw2[OSDIM];
    float betaw2[OSDIM];
    float rs2[OSDIM];           // rowsum(Ww2)
    float Wp1[9], bp1[3], gp[3], betap[3];
    float bw2sum;               // sum(bw2)
};

__constant__ CParams c_par;
__device__   CParams g_stage;

// Scratch (device globals: no allocation allowed)
__device__ __align__(256) float g_xq[NPTS * CDIM];
__device__ __align__(256) float g_xk[NPTS * CDIM];
__device__ __align__(256) float g_xv[NPTS * CDIM];

// ---------------------------------------------------------------------------
// Kernel 0: pack block-invariant params into g_stage (then D2D -> c_par).
// ---------------------------------------------------------------------------
__global__ void stage_kernel(const float* __restrict__ Wp1, const float* __restrict__ bp1,
                             const float* __restrict__ gp,  const float* __restrict__ betap,
                             const float* __restrict__ gw1, const float* __restrict__ betaw1,
                             const float* __restrict__ Ww1, const float* __restrict__ bw1,
                             const float* __restrict__ gw2, const float* __restrict__ betaw2,
                             const float* __restrict__ Ww2, const float* __restrict__ bw2)
{
    int t = threadIdx.x;   // 256 threads
    if (t < 256) g_stage.Ww1[t] = Ww1[t];
    if (t < 16) {
        g_stage.gw1[t]    = gw1[t];
        g_stage.betaw1[t] = betaw1[t];
        g_stage.bw1[t]    = bw1[t];
        g_stage.gw2[t]    = gw2[t];
        g_stage.betaw2[t] = betaw2[t];
        float rs = 0.f;
#pragma unroll
        for (int o = 0; o < OSDIM; o++) rs += Ww2[t * OSDIM + o];
        g_stage.rs2[t] = rs;
    }
    if (t < 9) g_stage.Wp1[t] = Wp1[t];
    if (t < 3) {
        g_stage.bp1[t]   = bp1[t];
        g_stage.gp[t]    = gp[t];
        g_stage.betap[t] = betap[t];
    }
    if (t == 0) {
        float sb = 0.f;
#pragma unroll
        for (int o = 0; o < OSDIM; o++) sb += bw2[o];
        g_stage.bw2sum = sb;
    }
}

// ---------------------------------------------------------------------------
// Kernel 1: fused QKV GEMM on tensor cores — single-pass TF32 (unchanged).
// ---------------------------------------------------------------------------
#define GTM 128
#define GTN 64
#define GTK 32
#define AS_STR 36
#define BS_STR 72
#define GEMM_SMEM_WORDS (GTM * AS_STR + GTK * BS_STR)
#define GEMM_SMEM_BYTES (GEMM_SMEM_WORDS * 4)

__global__ __launch_bounds__(256, 2)
void qkv_gemm_tf32(const float* __restrict__ x,
                   const float* __restrict__ Wq, const float* __restrict__ bq,
                   const float* __restrict__ Wk, const float* __restrict__ bk,
                   const float* __restrict__ Wv, const float* __restrict__ bv,
                   int row_base, int row_end)
{
    const float* W; const float* bias; float* dst;
    if (blockIdx.z == 0)      { W = Wq; bias = bq; dst = g_xq; }
    else if (blockIdx.z == 1) { W = Wk; bias = bk; dst = g_xk; }
    else                      { W = Wv; bias = bv; dst = g_xv; }

    extern __shared__ uint32_t smem_u[];
    uint32_t* As = smem_u;
    uint32_t* Bs = As + GTM * AS_STR;

    const int tid  = threadIdx.x;
    const int wid  = tid >> 5;
    const int lane = tid & 31;
    const int g    = lane >> 2;
    const int tg   = lane & 3;

    const int warp_m = wid & 3;
    const int warp_n = wid >> 2;
    const int row0 = row_base + blockIdx.x * GTM;
    const int col0 = blockIdx.y * GTN;

    float c[2][4][4];
#pragma unroll
    for (int mt = 0; mt < 2; mt++)
#pragma unroll
        for (int nt = 0; nt < 4; nt++)
#pragma unroll
            for (int q = 0; q < 4; q++) c[mt][nt][q] = 0.f;

    const int arow_ = tid >> 3;
    const int ak4   = (tid & 7) * 4;
    const int brow_ = tid >> 4;
    const int bn4   = (tid & 15) * 4;

    for (int kk = 0; kk < CDIM; kk += GTK) {
        __syncthreads();

#pragma unroll
        for (int ps = 0; ps < 4; ps++) {
            int m  = arow_ + ps * 32;
            int gr = row0 + m;
            float4 v = (gr < row_end)
                     ? *(const float4*)(x + (size_t)gr * CDIM + kk + ak4)
                     : make_float4(0.f, 0.f, 0.f, 0.f);
            uint4 hi;
            hi.x = f2tf(v.x); hi.y = f2tf(v.y);
            hi.z = f2tf(v.z); hi.w = f2tf(v.w);
            *(uint4*)&As[m * AS_STR + ak4] = hi;
        }
#pragma unroll
        for (int ps = 0; ps < 2; ps++) {
            int k = brow_ + ps * 16;
            float4 v = *(const float4*)(W + (size_t)(kk + k) * CDIM + col0 + bn4);
            uint4 hi;
            hi.x = f2tf(v.x); hi.y = f2tf(v.y);
            hi.z = f2tf(v.z); hi.w = f2tf(v.w);
            *(uint4*)&Bs[k * BS_STR + bn4] = hi;
        }
        __syncthreads();

#pragma unroll
        for (int ks = 0; ks < 4; ks++) {
            const int k0 = ks * 8;
            uint32_t ah[2][4], bh[4][2];
#pragma unroll
            for (int mt = 0; mt < 2; mt++) {
                int rb = warp_m * 32 + mt * 16 + g;
                int o  = rb * AS_STR + k0 + tg;
                ah[mt][0] = As[o];
                ah[mt][1] = As[o + 8 * AS_STR];
                ah[mt][2] = As[o + 4];
                ah[mt][3] = As[o + 8 * AS_STR + 4];
            }
#pragma unroll
            for (int nt = 0; nt < 4; nt++) {
                int cb = warp_n * 32 + nt * 8 + g;
                int o  = (k0 + tg) * BS_STR + cb;
                bh[nt][0] = Bs[o];
                bh[nt][1] = Bs[o + 4 * BS_STR];
            }
#pragma unroll
            for (int mt = 0; mt < 2; mt++)
#pragma unroll
                for (int nt = 0; nt < 4; nt++)
                    MMA_TF32(c[mt][nt], ah[mt], bh[nt]);
        }
    }

#pragma unroll
    for (int nt = 0; nt < 4; nt++) {
        int cn = col0 + warp_n * 32 + nt * 8 + 2 * tg;
        float2 bb = *(const float2*)(bias + cn);
#pragma unroll
        for (int mt = 0; mt < 2; mt++) {
            int gr0 = row0 + warp_m * 32 + mt * 16 + g;
            if (gr0 < row_end) {
                float2 o0 = make_float2(c[mt][nt][0] + bb.x, c[mt][nt][1] + bb.y);
                *(float2*)(dst + (size_t)gr0 * CDIM + cn) = o0;
            }
            int gr1 = gr0 + 8;
            if (gr1 < row_end) {
                float2 o1 = make_float2(c[mt][nt][2] + bb.x, c[mt][nt][3] + bb.y);
                *(float2*)(dst + (size_t)gr1 * CDIM + cn) = o1;
            }
        }
    }
}

// ---------------------------------------------------------------------------
// Kernel 2: per-point fused attention.
//   - __launch_bounds__(128, 14): regs<=36, occ 75%->87.5%
//   - divergently-indexed Wp2/bp2 in smem (LDS), uniform params via LDCU
//   - V loads moved after softmax (live-range cut), 4-wide chunks
//   - r kept packed through LN1 (no scalar r[16] array)
// ---------------------------------------------------------------------------
__global__ __launch_bounds__(128, 14)
void attn_kernel(const float* __restrict__ p,
                 const int*   __restrict__ idx,
                 const float* __restrict__ Wp2g,
                 const float* __restrict__ bp2g,
                 float* __restrict__ out,
                 int off)
{
    const int i   = blockIdx.x + off;
    const int tid = threadIdx.x;          // 0..127
    const int lane = tid & 31;

    __shared__ __align__(16) float skv[SNBR * CDIM];   // K gather, swizzled
    __shared__ __align__(16) float spp[4 * CDIM];      // Wp2 (384) + bp2 (128)
    __shared__ int sidx[SNBR];

    if (tid < SNBR) sidx[tid] = idx[i * SNBR + tid];

    // stage Wp2+bp2: one float4 per thread (Wp2 = 96 float4, bp2 = 32 float4)
    {
        float4 v = (tid < 96) ? __ldg((const float4*)Wp2g + tid)
                              : __ldg((const float4*)bp2g + (tid - 96));
        *(float4*)&spp[tid * 4] = v;
    }

    // --- gather K rows: warp-uniform row index via LDG, swizzled STS ---
    {
        const int warp = tid >> 5;
#pragma unroll
        for (int j = 0; j < 4; j++) {
            int sr  = warp * 4 + j;
            int row = __ldg(idx + i * SNBR + sr);          // uniform per warp
            float4 k4 = __ldg((const float4*)(g_xk + (size_t)row * CDIM) + lane);
            int g = lane ^ (sr & 7);
            *(float4*)&skv[sr * CDIM + g * 4] = k4;
        }
    }
    __syncthreads();

    const int s    = tid & 15;      // neighbor
    const int h    = tid >> 4;      // head
    const int base = h * DHEAD;

    // --- positional encoding front-end (uniform params via LDCU) ---
    const int nrow = sidx[s];
    float pr0 = p[nrow * 3 + 0] - p[i * 3 + 0];
    float pr1 = p[nrow * 3 + 1] - p[i * 3 + 1];
    float pr2 = p[nrow * 3 + 2] - p[i * 3 + 2];

    float t0 = pr0 * c_par.Wp1[0] + pr1 * c_par.Wp1[3] + pr2 * c_par.Wp1[6] + c_par.bp1[0];
    float t1 = pr0 * c_par.Wp1[1] + pr1 * c_par.Wp1[4] + pr2 * c_par.Wp1[7] + c_par.bp1[1];
    float t2 = pr0 * c_par.Wp1[2] + pr1 * c_par.Wp1[5] + pr2 * c_par.Wp1[8] + c_par.bp1[2];

    float m3 = (t0 + t1 + t2) * (1.f / 3.f);
    float d0 = t0 - m3, d1 = t1 - m3, d2 = t2 - m3;
    float v3 = (d0 * d0 + d1 * d1 + d2 * d2) * (1.f / 3.f);
    float rstd3 = rsqrtf(v3 + EPSV);
    float a0 = fmaxf(d0 * rstd3 * c_par.gp[0] + c_par.betap[0], 0.f);
    float a1 = fmaxf(d1 * rstd3 * c_par.gp[1] + c_par.betap[1], 0.f);
    float a2 = fmaxf(d2 * rstd3 * c_par.gp[2] + c_par.betap[2], 0.f);

    const u64 a0d = dup2(a0), a1d = dup2(a1), a2d = dup2(a2);
    const u64 neg1 = NEG1P;

    // --- r = k + pe - q (packed; Wp2/bp2 from smem = LDS broadcast) ---
    u64 rp[8];
    const ulonglong2* xq2 = (const ulonglong2*)(g_xq + (size_t)i * CDIM + base);
#pragma unroll
    for (int j = 0; j < 4; j++) {
        int g = ((h << 2) + j) ^ (s & 7);
        ulonglong2 kk = *(const ulonglong2*)&skv[s * CDIM + g * 4];
        ulonglong2 w0 = *(const ulonglong2*)&spp[base + j * 4];
        ulonglong2 w1 = *(const ulonglong2*)&spp[128 + base + j * 4];
        ulonglong2 w2 = *(const ulonglong2*)&spp[256 + base + j * 4];
        ulonglong2 bb = *(const ulonglong2*)&spp[384 + base + j * 4];
        ulonglong2 qq = __ldg(xq2 + j);

        u64 pe0, pe1, tmp;
        F32X2_FMA(tmp, a2d, w2.x, bb.x);
        F32X2_FMA(tmp, a1d, w1.x, tmp);
        F32X2_FMA(pe0, a0d, w0.x, tmp);
        F32X2_FMA(tmp, a2d, w2.y, bb.y);
        F32X2_FMA(tmp, a1d, w1.y, tmp);
        F32X2_FMA(pe1, a0d, w0.y, tmp);

        u64 r0, r1;
        F32X2_ADD(r0, kk.x, pe0);
        F32X2_FMA(r0, qq.x, neg1, r0);
        F32X2_ADD(r1, kk.y, pe1);
        F32X2_FMA(r1, qq.y, neg1, r1);
        rp[j * 2 + 0] = r0;
        rp[j * 2 + 1] = r1;
    }

    // --- LN over D (packed stats) + relu, result stays packed in rp ---
    {
        u64 sp = rp[0];
        F32X2_ADD(sp, sp, rp[1]); F32X2_ADD(sp, sp, rp[2]); F32X2_ADD(sp, sp, rp[3]);
        F32X2_ADD(sp, sp, rp[4]); F32X2_ADD(sp, sp, rp[5]); F32X2_ADD(sp, sp, rp[6]);
        F32X2_ADD(sp, sp, rp[7]);
        float2 sf = unpack2(sp);
        float mean = (sf.x + sf.y) * (1.f / DHEAD);
        u64 meanp = dup2(mean);
        u64 vp = 0ULL;
#pragma unroll
        for (int j = 0; j < 8; j++) {
            u64 dd;
            F32X2_FMA(dd, meanp, neg1, rp[j]);   // dd = r - mean
            F32X2_FMA(vp, dd, dd, vp);
            rp[j] = dd;
        }
        float2 vf = unpack2(vp);
        float rstd = rsqrtf((vf.x + vf.y) * (1.f / DHEAD) + EPSV);
        u64 rstdp = dup2(rstd);
        const u64* gwp = (const u64*)c_par.gw1;
        const u64* bwp = (const u64*)c_par.betaw1;
#pragma unroll
        for (int j = 0; j < 8; j++) {
            u64 rg, t;
            F32X2_MUL(rg, rstdp, gwp[j]);
            F32X2_FMA(t, rp[j], rg, bwp[j]);
            rp[j] = relu2(t);
        }
    }

    // --- w1 = relu_ln(r) @ Ww1 + bw1 (weights via LDCU; r unpacked inline) ---
    u64 w1p[8];
    {
        const u64* bw = (const u64*)c_par.bw1;
#pragma unroll
        for (int j = 0; j < 8; j++) w1p[j] = bw[j];
#pragma unroll
        for (int j = 0; j < 8; j++) {
            float2 rf = unpack2(rp[j]);          // register-pair alias: free
#pragma unroll
            for (int half = 0; half < 2; half++) {
                int d = 2 * j + half;
                u64 ud = dup2(half ? rf.y : rf.x);
                const ulonglong2* wr = (const ulonglong2*)&c_par.Ww1[d * OSDIM];
                ulonglong2 wa = wr[0], wb = wr[1], wc = wr[2], wd_ = wr[3];
                F32X2_FMA(w1p[0], ud, wa.x, w1p[0]);
                F32X2_FMA(w1p[1], ud, wa.y, w1p[1]);
                F32X2_FMA(w1p[2], ud, wb.x, w1p[2]);
                F32X2_FMA(w1p[3], ud, wb.y, w1p[3]);
                F32X2_FMA(w1p[4], ud, wc.x, w1p[4]);
                F32X2_FMA(w1p[5], ud, wc.y, w1p[5]);
                F32X2_FMA(w1p[6], ud, wd_.x, w1p[6]);
                F32X2_FMA(w1p[7], ud, wd_.y, w1p[7]);
            }
        }
    }

    // --- LN over OS (packed), relu ---
    {
        u64 sp = w1p[0];
        F32X2_ADD(sp, sp, w1p[1]); F32X2_ADD(sp, sp, w1p[2]); F32X2_ADD(sp, sp, w1p[3]);
        F32X2_ADD(sp, sp, w1p[4]); F32X2_ADD(sp, sp, w1p[5]); F32X2_ADD(sp, sp, w1p[6]);
        F32X2_ADD(sp, sp, w1p[7]);
        float2 sf = unpack2(sp);
        float mean = (sf.x + sf.y) * (1.f / OSDIM);
        u64 meanp = dup2(mean);
        u64 vp = 0ULL;
#pragma unroll
        for (int j = 0; j < 8; j++) {
            u64 dd;
            F32X2_FMA(dd, meanp, neg1, w1p[j]);
            F32X2_FMA(vp, dd, dd, vp);
            w1p[j] = dd;
        }
        float2 vf = unpack2(vp);
        float rstd = rsqrtf((vf.x + vf.y) * (1.f / OSDIM) + EPSV);
        u64 rstdp = dup2(rstd);
        const u64* gwp = (const u64*)c_par.gw2;
        const u64* bwp = (const u64*)c_par.betaw2;
#pragma unroll
        for (int j = 0; j < 8; j++) {
            u64 rg, t;
            F32X2_MUL(rg, rstdp, gwp[j]);
            F32X2_FMA(t, w1p[j], rg, bwp[j]);
            w1p[j] = relu2(t);
        }
    }

    // --- logit = (y @ rowsum(Ww2) + sum(bw2)) / 16 ---
    float logit;
    {
        const u64* rsp = (const u64*)c_par.rs2;
        u64 acc = 0ULL;
#pragma unroll
        for (int j = 0; j < 8; j++) F32X2_FMA(acc, w1p[j], rsp[j], acc);
        float2 af = unpack2(acc);
        logit = (af.x + af.y + c_par.bw2sum) * (1.f / OSDIM);
    }

    // --- softmax over s (16-lane butterfly) ---
    float mx = logit;
#pragma unroll
    for (int j = 8; j >= 1; j >>= 1)
        mx = fmaxf(mx, __shfl_xor_sync(0xffffffffu, mx, j));
    float e = __expf(logit - mx);
    float se = e;
#pragma unroll
    for (int j = 8; j >= 1; j >>= 1)
        se += __shfl_xor_sync(0xffffffffu, se, j);
    float w = __fdividef(e, se);

    // --- abar_t = sum_s w[h,s] * a_t[s] ---
    float wa0 = w * a0, wa1 = w * a1, wa2 = w * a2;
#pragma unroll
    for (int j = 8; j >= 1; j >>= 1) {
        wa0 += __shfl_xor_sync(0xffffffffu, wa0, j);
        wa1 += __shfl_xor_sync(0xffffffffu, wa1, j);
        wa2 += __shfl_xor_sync(0xffffffffu, wa2, j);
    }

    // --- V term: loads AFTER softmax (short live range), 4-wide chunks ---
    float acc = 0.f;
#pragma unroll
    for (int t4 = 0; t4 < SNBR; t4 += 4) {
        float v0 = __ldg(g_xv + (size_t)sidx[t4 + 0] * CDIM + tid);
        float v1 = __ldg(g_xv + (size_t)sidx[t4 + 1] * CDIM + tid);
        float v2 = __ldg(g_xv + (size_t)sidx[t4 + 2] * CDIM + tid);
        float v3_ = __ldg(g_xv + (size_t)sidx[t4 + 3] * CDIM + tid);
        acc = fmaf(__shfl_sync(0xffffffffu, w, (lane & 16) | (t4 + 0)), v0, acc);
        acc = fmaf(__shfl_sync(0xffffffffu, w, (lane & 16) | (t4 + 1)), v1, acc);
        acc = fmaf(__shfl_sync(0xffffffffu, w, (lane & 16) | (t4 + 2)), v2, acc);
        acc = fmaf(__shfl_sync(0xffffffffu, w, (lane & 16) | (t4 + 3)), v3_, acc);
    }

    // --- folded pe term: abar @ Wp2[:,c] + bp2[c] (smem, tid-indexed) ---
    float peo = spp[384 + tid];
    peo = fmaf(wa2, spp[256 + tid], peo);
    peo = fmaf(wa1, spp[128 + tid], peo);
    peo = fmaf(wa0, spp[tid],       peo);

    out[(size_t)i * CDIM + tid] = acc + peo;
}

// ---------------------------------------------------------------------------
// Launch: two-stream fork/join (unchanged topology).
// ---------------------------------------------------------------------------
extern "C" void kernel_launch(void* const* d_in, const int* in_sizes, int n_in,
                              void* d_out, int out_size)
{
    const float* p      = (const float*)d_in[0];
    const float* x      = (const float*)d_in[1];
    const int*   idx    = (const int*)  d_in[2];
    const float* Wq     = (const float*)d_in[3];
    const float* bq     = (const float*)d_in[4];
    const float* Wk     = (const float*)d_in[5];
    const float* bk     = (const float*)d_in[6];
    const float* Wv     = (const float*)d_in[7];
    const float* bv     = (const float*)d_in[8];
    const float* Wp1    = (const float*)d_in[9];
    const float* bp1    = (const float*)d_in[10];
    const float* gp     = (const float*)d_in[11];
    const float* betap  = (const float*)d_in[12];
    const float* Wp2    = (const float*)d_in[13];
    const float* bp2    = (const float*)d_in[14];
    const float* gw1    = (const float*)d_in[15];
    const float* betaw1 = (const float*)d_in[16];
    const float* Ww1    = (const float*)d_in[17];
    const float* bw1    = (const float*)d_in[18];
    const float* gw2    = (const float*)d_in[19];
    const float* betaw2 = (const float*)d_in[20];
    const float* Ww2    = (const float*)d_in[21];
    const float* bw2    = (const float*)d_in[22];
    float* out = (float*)d_out;

    static cudaStream_t s2 = nullptr;
    static cudaEvent_t evFork, evG0, evG1;
    if (!s2) {
        cudaStreamCreateWithFlags(&s2, cudaStreamNonBlocking);
        cudaEventCreateWithFlags(&evFork, cudaEventDisableTiming);
        cudaEventCreateWithFlags(&evG0, cudaEventDisableTiming);
        cudaEventCreateWithFlags(&evG1, cudaEventDisableTiming);
        cudaFuncSetAttribute(qkv_gemm_tf32,
                             cudaFuncAttributeMaxDynamicSharedMemorySize,
                             GEMM_SMEM_BYTES);
    }

    // Fork s2 from the (captured) default stream.
    cudaEventRecord(evFork, 0);
    cudaStreamWaitEvent(s2, evFork, 0);

    // s2: GEMM half0 then half1.
    dim3 ggrid((NHALF + GTM - 1) / GTM, CDIM / GTN, 3);
    qkv_gemm_tf32<<<ggrid, 256, GEMM_SMEM_BYTES, s2>>>(
        x, Wq, bq, Wk, bk, Wv, bv, 0, NHALF);
    cudaEventRecord(evG0, s2);
    qkv_gemm_tf32<<<ggrid, 256, GEMM_SMEM_BYTES, s2>>>(
        x, Wq, bq, Wk, bk, Wv, bv, NHALF, NPTS);
    cudaEventRecord(evG1, s2);

    // default: stage params + copy to constant bank (overlaps gemm half0).
    stage_kernel<<<1, 256>>>(Wp1, bp1, gp, betap,
                             gw1, betaw1, Ww1, bw1, gw2, betaw2, Ww2, bw2);
    void* stage_addr = nullptr;
    cudaGetSymbolAddress(&stage_addr, g_stage);
    cudaMemcpyToSymbolAsync(c_par, stage_addr, sizeof(CParams), 0,
                            cudaMemcpyDeviceToDevice, 0);

    // default: attn half0 (needs gemm half0), overlaps gemm half1.
    cudaStreamWaitEvent(0, evG0, 0);
    attn_kernel<<<NHALF, 128>>>(p, idx, Wp2, bp2, out, 0);

    // default: attn half1 (needs gemm half1); joins s2 back into capture.
    cudaStreamWaitEvent(0, evG1, 0);
    attn_kernel<<<NHALF, 128>>>(p, idx, Wp2, bp2, out, NHALF);
}

// round 15
// speedup vs baseline: 1.0802x; 1.0802x over previous
#include <cuda_runtime.h>
#include <cstdint>

#define NPTS 30000
#define NHALF 15000
#define CDIM 128
#define HEADS 8
#define DHEAD 16
#define SNBR 16
#define OSDIM 16
#define EPSV 1e-5f

typedef unsigned long long u64;

// packed f32x2 helpers (FFMA2 path — PTX-only on sm_103a)
#define F32X2_FMA(d, a, b, c) \
    asm("fma.rn.f32x2 %0, %1, %2, %3;" : "=l"(d) : "l"(a), "l"(b), "l"(c))
#define F32X2_ADD(d, a, b) \
    asm("add.rn.f32x2 %0, %1, %2;" : "=l"(d) : "l"(a), "l"(b))
#define F32X2_MUL(d, a, b) \
    asm("mul.rn.f32x2 %0, %1, %2;" : "=l"(d) : "l"(a), "l"(b))

__device__ __forceinline__ u64 pack2(float lo, float hi) {
    u64 r; asm("mov.b64 %0, {%1, %2};" : "=l"(r) : "f"(lo), "f"(hi)); return r;
}
__device__ __forceinline__ u64 dup2(float x) {
    u64 r; asm("mov.b64 %0, {%1, %1};" : "=l"(r) : "f"(x)); return r;
}
__device__ __forceinline__ float2 unpack2(u64 v) {
    float lo, hi; asm("mov.b64 {%0, %1}, %2;" : "=f"(lo), "=f"(hi) : "l"(v));
    return make_float2(lo, hi);
}
__device__ __forceinline__ u64 relu2(u64 x) {
    float2 f = unpack2(x);
    return pack2(fmaxf(f.x, 0.f), fmaxf(f.y, 0.f));
}

#define NEG1P 0xBF800000BF800000ULL   // (-1.0f, -1.0f)

// tf32 helpers
__device__ __forceinline__ uint32_t f2tf(float f) {
    uint32_t r; asm("cvt.rna.tf32.f32 %0, %1;" : "=r"(r) : "f"(f)); return r;
}
#define MMA_TF32(c, a, b) \
    asm("mma.sync.aligned.m16n8k8.row.col.f32.tf32.tf32.f32 " \
        "{%0,%1,%2,%3}, {%4,%5,%6,%7}, {%8,%9}, {%0,%1,%2,%3};" \
        : "+f"((c)[0]), "+f"((c)[1]), "+f"((c)[2]), "+f"((c)[3]) \
        : "r"((a)[0]), "r"((a)[1]), "r"((a)[2]), "r"((a)[3]), \
          "r"((b)[0]), "r"((b)[1]))

// ---------------------------------------------------------------------------
// Block-invariant parameters in the constant bank (R13 layout — proven).
// ---------------------------------------------------------------------------
struct __align__(16) CParams {
    float Ww1[DHEAD * OSDIM];   // 256
    float Wp2[3 * CDIM];        // 384
    float bp2[CDIM];            // 128
    float gw1[DHEAD];
    float betaw1[DHEAD];
    float bw1[OSDIM];
    float gw2[OSDIM];
    float betaw2[OSDIM];
    float rs2[OSDIM];           // rowsum(Ww2)
    float Wp1[9], bp1[3], gp[3], betap[3];
    float bw2sum;               // sum(bw2)
};

__constant__ CParams c_par;
__device__   CParams g_stage;

// Scratch (device globals: no allocation allowed)
__device__ __align__(256) float g_xq[NPTS * CDIM];
__device__ __align__(256) float g_xk[NPTS * CDIM];
__device__ __align__(256) float g_xv[NPTS * CDIM];

// ---------------------------------------------------------------------------
// Kernel 0: pack block-invariant params into g_stage (then D2D -> c_par).
// ---------------------------------------------------------------------------
__global__ void stage_kernel(const float* __restrict__ Wp1, const float* __restrict__ bp1,
                             const float* __restrict__ gp,  const float* __restrict__ betap,
                             const float* __restrict__ Wp2, const float* __restrict__ bp2,
                             const float* __restrict__ gw1, const float* __restrict__ betaw1,
                             const float* __restrict__ Ww1, const float* __restrict__ bw1,
                             const float* __restrict__ gw2, const float* __restrict__ betaw2,
                             const float* __restrict__ Ww2, const float* __restrict__ bw2)
{
    int t = threadIdx.x;   // 384 threads
    if (t < 384) g_stage.Wp2[t] = Wp2[t];
    if (t < 256) g_stage.Ww1[t] = Ww1[t];
    if (t < 128) g_stage.bp2[t] = bp2[t];
    if (t < 16) {
        g_stage.gw1[t]    = gw1[t];
        g_stage.betaw1[t] = betaw1[t];
        g_stage.bw1[t]    = bw1[t];
        g_stage.gw2[t]    = gw2[t];
        g_stage.betaw2[t] = betaw2[t];
        float rs = 0.f;
#pragma unroll
        for (int o = 0; o < OSDIM; o++) rs += Ww2[t * OSDIM + o];
        g_stage.rs2[t] = rs;
    }
    if (t < 9) g_stage.Wp1[t] = Wp1[t];
    if (t < 3) {
        g_stage.bp1[t]   = bp1[t];
        g_stage.gp[t]    = gp[t];
        g_stage.betap[t] = betap[t];
    }
    if (t == 0) {
        float sb = 0.f;
#pragma unroll
        for (int o = 0; o < OSDIM; o++) sb += bw2[o];
        g_stage.bw2sum = sb;
    }
}

// ---------------------------------------------------------------------------
// Kernel 1: fused QKV GEMM on tensor cores — single-pass TF32 (R13, proven).
// ---------------------------------------------------------------------------
#define GTM 128
#define GTN 64
#define GTK 32
#define AS_STR 36
#define BS_STR 72
#define GEMM_SMEM_WORDS (GTM * AS_STR + GTK * BS_STR)
#define GEMM_SMEM_BYTES (GEMM_SMEM_WORDS * 4)

__global__ __launch_bounds__(256, 2)
void qkv_gemm_tf32(const float* __restrict__ x,
                   const float* __restrict__ Wq, const float* __restrict__ bq,
                   const float* __restrict__ Wk, const float* __restrict__ bk,
                   const float* __restrict__ Wv, const float* __restrict__ bv,
                   int row_base, int row_end)
{
    const float* W; const float* bias; float* dst;
    if (blockIdx.z == 0)      { W = Wq; bias = bq; dst = g_xq; }
    else if (blockIdx.z == 1) { W = Wk; bias = bk; dst = g_xk; }
    else                      { W = Wv; bias = bv; dst = g_xv; }

    extern __shared__ uint32_t smem_u[];
    uint32_t* As = smem_u;
    uint32_t* Bs = As + GTM * AS_STR;

    const int tid  = threadIdx.x;
    const int wid  = tid >> 5;
    const int lane = tid & 31;
    const int g    = lane >> 2;
    const int tg   = lane & 3;

    const int warp_m = wid & 3;
    const int warp_n = wid >> 2;
    const int row0 = row_base + blockIdx.x * GTM;
    const int col0 = blockIdx.y * GTN;

    float c[2][4][4];
#pragma unroll
    for (int mt = 0; mt < 2; mt++)
#pragma unroll
        for (int nt = 0; nt < 4; nt++)
#pragma unroll
            for (int q = 0; q < 4; q++) c[mt][nt][q] = 0.f;

    const int arow_ = tid >> 3;
    const int ak4   = (tid & 7) * 4;
    const int brow_ = tid >> 4;
    const int bn4   = (tid & 15) * 4;

    for (int kk = 0; kk < CDIM; kk += GTK) {
        __syncthreads();

#pragma unroll
        for (int ps = 0; ps < 4; ps++) {
            int m  = arow_ + ps * 32;
            int gr = row0 + m;
            float4 v = (gr < row_end)
                     ? *(const float4*)(x + (size_t)gr * CDIM + kk + ak4)
                     : make_float4(0.f, 0.f, 0.f, 0.f);
            uint4 hi;
            hi.x = f2tf(v.x); hi.y = f2tf(v.y);
            hi.z = f2tf(v.z); hi.w = f2tf(v.w);
            *(uint4*)&As[m * AS_STR + ak4] = hi;
        }
#pragma unroll
        for (int ps = 0; ps < 2; ps++) {
            int k = brow_ + ps * 16;
            float4 v = *(const float4*)(W + (size_t)(kk + k) * CDIM + col0 + bn4);
            uint4 hi;
            hi.x = f2tf(v.x); hi.y = f2tf(v.y);
            hi.z = f2tf(v.z); hi.w = f2tf(v.w);
            *(uint4*)&Bs[k * BS_STR + bn4] = hi;
        }
        __syncthreads();

#pragma unroll
        for (int ks = 0; ks < 4; ks++) {
            const int k0 = ks * 8;
            uint32_t ah[2][4], bh[4][2];
#pragma unroll
            for (int mt = 0; mt < 2; mt++) {
                int rb = warp_m * 32 + mt * 16 + g;
                int o  = rb * AS_STR + k0 + tg;
                ah[mt][0] = As[o];
                ah[mt][1] = As[o + 8 * AS_STR];
                ah[mt][2] = As[o + 4];
                ah[mt][3] = As[o + 8 * AS_STR + 4];
            }
#pragma unroll
            for (int nt = 0; nt < 4; nt++) {
                int cb = warp_n * 32 + nt * 8 + g;
                int o  = (k0 + tg) * BS_STR + cb;
                bh[nt][0] = Bs[o];
                bh[nt][1] = Bs[o + 4 * BS_STR];
            }
#pragma unroll
            for (int mt = 0; mt < 2; mt++)
#pragma unroll
                for (int nt = 0; nt < 4; nt++)
                    MMA_TF32(c[mt][nt], ah[mt], bh[nt]);
        }
    }

#pragma unroll
    for (int nt = 0; nt < 4; nt++) {
        int cn = col0 + warp_n * 32 + nt * 8 + 2 * tg;
        float2 bb = *(const float2*)(bias + cn);
#pragma unroll
        for (int mt = 0; mt < 2; mt++) {
            int gr0 = row0 + warp_m * 32 + mt * 16 + g;
            if (gr0 < row_end) {
                float2 o0 = make_float2(c[mt][nt][0] + bb.x, c[mt][nt][1] + bb.y);
                *(float2*)(dst + (size_t)gr0 * CDIM + cn) = o0;
            }
            int gr1 = gr0 + 8;
            if (gr1 < row_end) {
                float2 o1 = make_float2(c[mt][nt][2] + bb.x, c[mt][nt][3] + bb.y);
                *(float2*)(dst + (size_t)gr1 * CDIM + cn) = o1;
            }
        }
    }
}

// ---------------------------------------------------------------------------
// Kernel 2: per-point fused attention — exact R13 version (proven 57.3us/half:
// regs 40, V prefetch before softmax, params via constant bank).
// ---------------------------------------------------------------------------
__global__ __launch_bounds__(128)
void attn_kernel(const float* __restrict__ p,
                 const int*   __restrict__ idx,
                 const float* __restrict__ Wp2g,
                 const float* __restrict__ bp2g,
                 float* __restrict__ out,
                 int off)
{
    const int i   = blockIdx.x + off;
    const int tid = threadIdx.x;          // 0..127
    const int lane = tid & 31;

    __shared__ __align__(16) float skv[SNBR * CDIM];   // K only, swizzled
    __shared__ int sidx[SNBR];

    if (tid < SNBR) sidx[tid] = idx[i * SNBR + tid];

    // --- gather K rows: warp-uniform row index via LDG, swizzled STS ---
    {
        const int warp = tid >> 5;
#pragma unroll
        for (int j = 0; j < 4; j++) {
            int sr  = warp * 4 + j;
            int row = __ldg(idx + i * SNBR + sr);          // uniform per warp
            float4 k4 = __ldg((const float4*)(g_xk + (size_t)row * CDIM) + lane);
            int g = lane ^ (sr & 7);
            *(float4*)&skv[sr * CDIM + g * 4] = k4;
        }
    }
    __syncthreads();

    const int s    = tid & 15;      // neighbor
    const int h    = tid >> 4;      // head
    const int base = h * DHEAD;

    // --- positional encoding front-end (params via constant bank) ---
    const int nrow = sidx[s];
    float pr0 = p[nrow * 3 + 0] - p[i * 3 + 0];
    float pr1 = p[nrow * 3 + 1] - p[i * 3 + 1];
    float pr2 = p[nrow * 3 + 2] - p[i * 3 + 2];

    float t0 = pr0 * c_par.Wp1[0] + pr1 * c_par.Wp1[3] + pr2 * c_par.Wp1[6] + c_par.bp1[0];
    float t1 = pr0 * c_par.Wp1[1] + pr1 * c_par.Wp1[4] + pr2 * c_par.Wp1[7] + c_par.bp1[1];
    float t2 = pr0 * c_par.Wp1[2] + pr1 * c_par.Wp1[5] + pr2 * c_par.Wp1[8] + c_par.bp1[2];

    float m3 = (t0 + t1 + t2) * (1.f / 3.f);
    float d0 = t0 - m3, d1 = t1 - m3, d2 = t2 - m3;
    float v3 = (d0 * d0 + d1 * d1 + d2 * d2) * (1.f / 3.f);
    float rstd3 = rsqrtf(v3 + EPSV);
    float a0 = fmaxf(d0 * rstd3 * c_par.gp[0] + c_par.betap[0], 0.f);
    float a1 = fmaxf(d1 * rstd3 * c_par.gp[1] + c_par.betap[1], 0.f);
    float a2 = fmaxf(d2 * rstd3 * c_par.gp[2] + c_par.betap[2], 0.f);

    const u64 a0d = dup2(a0), a1d = dup2(a1), a2d = dup2(a2);
    const u64 neg1 = NEG1P;

    // --- r = k + pe - q (packed) ---
    u64 rp[8];
    const ulonglong2* xq2 = (const ulonglong2*)(g_xq + (size_t)i * CDIM + base);
#pragma unroll
    for (int j = 0; j < 4; j++) {
        int g = ((h << 2) + j) ^ (s & 7);
        ulonglong2 kk = *(const ulonglong2*)&skv[s * CDIM + g * 4];
        ulonglong2 w0 = *(const ulonglong2*)&c_par.Wp2[base + j * 4];
        ulonglong2 w1 = *(const ulonglong2*)&c_par.Wp2[128 + base + j * 4];
        ulonglong2 w2 = *(const ulonglong2*)&c_par.Wp2[256 + base + j * 4];
        ulonglong2 bb = *(const ulonglong2*)&c_par.bp2[base + j * 4];
        ulonglong2 qq = __ldg(xq2 + j);

        u64 pe0, pe1, tmp;
        F32X2_FMA(tmp, a2d, w2.x, bb.x);
        F32X2_FMA(tmp, a1d, w1.x, tmp);
        F32X2_FMA(pe0, a0d, w0.x, tmp);
        F32X2_FMA(tmp, a2d, w2.y, bb.y);
        F32X2_FMA(tmp, a1d, w1.y, tmp);
        F32X2_FMA(pe1, a0d, w0.y, tmp);

        u64 r0, r1;
        F32X2_ADD(r0, kk.x, pe0);
        F32X2_FMA(r0, qq.x, neg1, r0);
        F32X2_ADD(r1, kk.y, pe1);
        F32X2_FMA(r1, qq.y, neg1, r1);
        rp[j * 2 + 0] = r0;
        rp[j * 2 + 1] = r1;
    }

    // --- LN over D (packed stats), relu -> scalar r[16] ---
    float r[DHEAD];
    {
        u64 sp = rp[0];
        F32X2_ADD(sp, sp, rp[1]); F32X2_ADD(sp, sp, rp[2]); F32X2_ADD(sp, sp, rp[3]);
        F32X2_ADD(sp, sp, rp[4]); F32X2_ADD(sp, sp, rp[5]); F32X2_ADD(sp, sp, rp[6]);
        F32X2_ADD(sp, sp, rp[7]);
        float2 sf = unpack2(sp);
        float mean = (sf.x + sf.y) * (1.f / DHEAD);
        u64 meanp = dup2(mean);
        u64 vp = 0ULL;
#pragma unroll
        for (int j = 0; j < 8; j++) {
            u64 dd;
            F32X2_FMA(dd, meanp, neg1, rp[j]);   // dd = r - mean
            F32X2_FMA(vp, dd, dd, vp);
            rp[j] = dd;
        }
        float2 vf = unpack2(vp);
        float rstd = rsqrtf((vf.x + vf.y) * (1.f / DHEAD) + EPSV);
        u64 rstdp = dup2(rstd);
        const u64* gwp = (const u64*)c_par.gw1;
        const u64* bwp = (const u64*)c_par.betaw1;
#pragma unroll
        for (int j = 0; j < 8; j++) {
            u64 rg, t;
            F32X2_MUL(rg, rstdp, gwp[j]);
            F32X2_FMA(t, rp[j], rg, bwp[j]);
            float2 tf = unpack2(t);
            r[2 * j + 0] = fmaxf(tf.x, 0.f);
            r[2 * j + 1] = fmaxf(tf.y, 0.f);
        }
    }

    // --- w1 = relu_ln(r) @ Ww1 + bw1 (weights via constant port) ---
    u64 w1p[8];
    {
        const u64* bw = (const u64*)c_par.bw1;
#pragma unroll
        for (int j = 0; j < 8; j++) w1p[j] = bw[j];
#pragma unroll
        for (int d = 0; d < DHEAD; d++) {
            u64 ud = dup2(r[d]);
            const ulonglong2* wr = (const ulonglong2*)&c_par.Ww1[d * OSDIM];
            ulonglong2 wa = wr[0], wb = wr[1], wc = wr[2], wd_ = wr[3];
            F32X2_FMA(w1p[0], ud, wa.x, w1p[0]);
            F32X2_FMA(w1p[1], ud, wa.y, w1p[1]);
            F32X2_FMA(w1p[2], ud, wb.x, w1p[2]);
            F32X2_FMA(w1p[3], ud, wb.y, w1p[3]);
            F32X2_FMA(w1p[4], ud, wc.x, w1p[4]);
            F32X2_FMA(w1p[5], ud, wc.y, w1p[5]);
            F32X2_FMA(w1p[6], ud, wd_.x, w1p[6]);
            F32X2_FMA(w1p[7], ud, wd_.y, w1p[7]);
        }
    }

    // --- LN over OS (packed), relu ---
    {
        u64 sp = w1p[0];
        F32X2_ADD(sp, sp, w1p[1]); F32X2_ADD(sp, sp, w1p[2]); F32X2_ADD(sp, sp, w1p[3]);
        F32X2_ADD(sp, sp, w1p[4]); F32X2_ADD(sp, sp, w1p[5]); F32X2_ADD(sp, sp, w1p[6]);
        F32X2_ADD(sp, sp, w1p[7]);
        float2 sf = unpack2(sp);
        float mean = (sf.x + sf.y) * (1.f / OSDIM);
        u64 meanp = dup2(mean);
        u64 vp = 0ULL;
#pragma unroll
        for (int j = 0; j < 8; j++) {
            u64 dd;
            F32X2_FMA(dd, meanp, neg1, w1p[j]);
            F32X2_FMA(vp, dd, dd, vp);
            w1p[j] = dd;
        }
        float2 vf = unpack2(vp);
        float rstd = rsqrtf((vf.x + vf.y) * (1.f / OSDIM) + EPSV);
        u64 rstdp = dup2(rstd);
        const u64* gwp = (const u64*)c_par.gw2;
        const u64* bwp = (const u64*)c_par.betaw2;
#pragma unroll
        for (int j = 0; j < 8; j++) {
            u64 rg, t;
            F32X2_MUL(rg, rstdp, gwp[j]);
            F32X2_FMA(t, w1p[j], rg, bwp[j]);
            w1p[j] = relu2(t);
        }
    }

    // --- logit = (y @ rowsum(Ww2) + sum(bw2)) / 16 ---
    float logit;
    {
        const u64* rsp = (const u64*)c_par.rs2;
        u64 acc = 0ULL;
#pragma unroll
        for (int j = 0; j < 8; j++) F32X2_FMA(acc, w1p[j], rsp[j], acc);
        float2 af = unpack2(acc);
        logit = (af.x + af.y + c_par.bw2sum) * (1.f / OSDIM);
    }

    // --- prefetch V column (channel tid of each neighbor row) ---
    float vv[SNBR];
#pragma unroll
    for (int t = 0; t < SNBR; t++) {
        int row = sidx[t];
        vv[t] = __ldg(g_xv + (size_t)row * CDIM + tid);
    }

    // --- softmax over s (16-lane butterfly) ---
    float mx = logit;
#pragma unroll
    for (int j = 8; j >= 1; j >>= 1)
        mx = fmaxf(mx, __shfl_xor_sync(0xffffffffu, mx, j));
    float e = __expf(logit - mx);
    float se = e;
#pragma unroll
    for (int j = 8; j >= 1; j >>= 1)
        se += __shfl_xor_sync(0xffffffffu, se, j);
    float w = __fdividef(e, se);

    // --- abar_t = sum_s w[h,s] * a_t[s] ---
    float wa0 = w * a0, wa1 = w * a1, wa2 = w * a2;
#pragma unroll
    for (int j = 8; j >= 1; j >>= 1) {
        wa0 += __shfl_xor_sync(0xffffffffu, wa0, j);
        wa1 += __shfl_xor_sync(0xffffffffu, wa1, j);
        wa2 += __shfl_xor_sync(0xffffffffu, wa2, j);
    }

    // --- V term: out_c = sum_s w[h,s]*xv[row_s][c]; weights via shfl ---
    float acc = 0.f;
#pragma unroll
    for (int t = 0; t < SNBR; t++) {
        float wt = __shfl_sync(0xffffffffu, w, (lane & 16) | t);
        acc = fmaf(wt, vv[t], acc);
    }

    // --- folded pe term: abar @ Wp2[:,c] + bp2[c] ---
    float peo = __ldg(bp2g + tid);
    peo = fmaf(wa2, __ldg(Wp2g + 256 + tid), peo);
    peo = fmaf(wa1, __ldg(Wp2g + 128 + tid), peo);
    peo = fmaf(wa0, __ldg(Wp2g + tid),       peo);

    out[(size_t)i * CDIM + tid] = acc + peo;
}

// ---------------------------------------------------------------------------
// Launch: fork/join with attn1 moved onto s2 (follows gemm1 in-stream), so
// attn0 and attn1 overlap at their boundary (tail-wave fill). attn1 waits on
// the c_par memcpy via evC; default joins s2 via evA at the end.
// ---------------------------------------------------------------------------
extern "C" void kernel_launch(void* const* d_in, const int* in_sizes, int n_in,
                              void* d_out, int out_size)
{
    const float* p      = (const float*)d_in[0];
    const float* x      = (const float*)d_in[1];
    const int*   idx    = (const int*)  d_in[2];
    const float* Wq     = (const float*)d_in[3];
    const float* bq     = (const float*)d_in[4];
    const float* Wk     = (const float*)d_in[5];
    const float* bk     = (const float*)d_in[6];
    const float* Wv     = (const float*)d_in[7];
    const float* bv     = (const float*)d_in[8];
    const float* Wp1    = (const float*)d_in[9];
    const float* bp1    = (const float*)d_in[10];
    const float* gp     = (const float*)d_in[11];
    const float* betap  = (const float*)d_in[12];
    const float* Wp2    = (const float*)d_in[13];
    const float* bp2    = (const float*)d_in[14];
    const float* gw1    = (const float*)d_in[15];
    const float* betaw1 = (const float*)d_in[16];
    const float* Ww1    = (const float*)d_in[17];
    const float* bw1    = (const float*)d_in[18];
    const float* gw2    = (const float*)d_in[19];
    const float* betaw2 = (const float*)d_in[20];
    const float* Ww2    = (const float*)d_in[21];
    const float* bw2    = (const float*)d_in[22];
    float* out = (float*)d_out;

    static cudaStream_t s2 = nullptr;
    static cudaEvent_t evFork, evG0, evC, evA;
    if (!s2) {
        cudaStreamCreateWithFlags(&s2, cudaStreamNonBlocking);
        cudaEventCreateWithFlags(&evFork, cudaEventDisableTiming);
        cudaEventCreateWithFlags(&evG0, cudaEventDisableTiming);
        cudaEventCreateWithFlags(&evC, cudaEventDisableTiming);
        cudaEventCreateWithFlags(&evA, cudaEventDisableTiming);
        cudaFuncSetAttribute(qkv_gemm_tf32,
                             cudaFuncAttributeMaxDynamicSharedMemorySize,
                             GEMM_SMEM_BYTES);
    }

    // Fork s2 from the (captured) default stream.
    cudaEventRecord(evFork, 0);
    cudaStreamWaitEvent(s2, evFork, 0);

    // s2: GEMM half0 -> GEMM half1.
    dim3 ggrid((NHALF + GTM - 1) / GTM, CDIM / GTN, 3);
    qkv_gemm_tf32<<<ggrid, 256, GEMM_SMEM_BYTES, s2>>>(
        x, Wq, bq, Wk, bk, Wv, bv, 0, NHALF);
    cudaEventRecord(evG0, s2);
    qkv_gemm_tf32<<<ggrid, 256, GEMM_SMEM_BYTES, s2>>>(
        x, Wq, bq, Wk, bk, Wv, bv, NHALF, NPTS);

    // default: stage params + copy to constant bank (overlaps gemm half0).
    stage_kernel<<<1, 384>>>(Wp1, bp1, gp, betap, Wp2, bp2,
                             gw1, betaw1, Ww1, bw1, gw2, betaw2, Ww2, bw2);
    void* stage_addr = nullptr;
    cudaGetSymbolAddress(&stage_addr, g_stage);
    cudaMemcpyToSymbolAsync(c_par, stage_addr, sizeof(CParams), 0,
                            cudaMemcpyDeviceToDevice, 0);
    cudaEventRecord(evC, 0);

    // s2: attn half1 right after gemm half1 (in-stream dep), after c_par copy.
    cudaStreamWaitEvent(s2, evC, 0);
    attn_kernel<<<NHALF, 128, 0, s2>>>(p, idx, Wp2, bp2, out, NHALF);
    cudaEventRecord(evA, s2);

    // default: attn half0 (needs gemm half0); overlaps gemm half1 + attn half1.
    cudaStreamWaitEvent(0, evG0, 0);
    attn_kernel<<<NHALF, 128>>>(p, idx, Wp2, bp2, out, 0);

    // Join s2 back into the capture stream.
    cudaStreamWaitEvent(0, evA, 0);
}